// round 5
// baseline (speedup 1.0000x reference)
#include <cuda_runtime.h>
#include <cuda_bf16.h>
#include <mma.h>
#include <cstdint>

using namespace nvcuda;

// Problem constants (fixed by the reference: N=4096, K=8, D=1024)
#define NROWS 4096
#define DDIM  1024
#define NNEG  3679            // int(0.9 * (4096 - 8))
#define HALF_CNT 7534592u     // (4096*3679)/2 == 2048*3679
#define MARGIN 0.15f
#define NTILE  32             // 4096/128 tiles per dim
#define NTRI   528            // NTILE*(NTILE+1)/2 upper-triangular tiles

// Scratch (device globals: allocation-free rule)
__device__ __align__(16) __nv_bfloat16 g_xn[NROWS * DDIM];           // 8 MB normalized bf16
__device__ __align__(16) float         g_cos[(size_t)NROWS * NROWS]; // 64 MB cosine matrix
__device__ float                       g_partial[2048];

// ---------------------------------------------------------------------------
// Kernel 1: row L2-normalize (with torch/jax EPS clamp) -> bf16
// ---------------------------------------------------------------------------
__global__ __launch_bounds__(256) void norm_kernel(const float* __restrict__ x) {
    __shared__ float red[8];
    int i = blockIdx.x, tid = threadIdx.x;
    float4 v = ((const float4*)(x + (size_t)i * DDIM))[tid];
    float ss = v.x * v.x + v.y * v.y + v.z * v.z + v.w * v.w;
    #pragma unroll
    for (int o = 16; o; o >>= 1) ss += __shfl_down_sync(0xffffffffu, ss, o);
    if ((tid & 31) == 0) red[tid >> 5] = ss;
    __syncthreads();
    if (tid < 8) {
        float t = red[tid];
        t += __shfl_down_sync(0xffu, t, 4);
        t += __shfl_down_sync(0xffu, t, 2);
        t += __shfl_down_sync(0xffu, t, 1);
        if (tid == 0) red[0] = t;
    }
    __syncthreads();
    float inv = 1.0f / fmaxf(sqrtf(red[0]), 1e-8f);
    __nv_bfloat162* dst = (__nv_bfloat162*)(g_xn + (size_t)i * DDIM + tid * 4);
    dst[0] = __floats2bfloat162_rn(v.x * inv, v.y * inv);
    dst[1] = __floats2bfloat162_rn(v.z * inv, v.w * inv);
}

// ---------------------------------------------------------------------------
// Kernel 2: C = Xn * Xn^T (cosine matrix), bf16 WMMA, fp32 accum.
// SYMMETRIC: only the 528 upper-triangular 128x128 tiles are computed;
// off-diagonal tiles are written twice (normal + col_major transposed store).
// 2-stage smem double buffer (one __syncthreads per K-iter) + register-staged
// global prefetch: STS of tile it+1 overlaps the HMMA section of tile it.
// ---------------------------------------------------------------------------
#define BK 32
#define SMS 40   // smem row stride (elements): 80B, 16B-multiple, conflict-free ldmatrix

__global__ __launch_bounds__(256) void gemm_kernel() {
    __shared__ __align__(16) __nv_bfloat16 As[2][128][SMS];
    __shared__ __align__(16) __nv_bfloat16 Bs[2][128][SMS];

    // map linear block id -> upper-triangular (by, bx), bx >= by
    int lin = blockIdx.x;              // 0..527
    int by = 0, rem = lin;
    while (rem >= NTILE - by) { rem -= NTILE - by; by++; }
    int bx = by + rem;

    int tid = threadIdx.x;
    int warp = tid >> 5;
    int wr = warp & 1;     // M sub (64 rows)
    int wc = warp >> 1;    // N sub (32 cols)

    wmma::fragment<wmma::accumulator, 16, 16, 16, float> acc[4][2];
    #pragma unroll
    for (int a = 0; a < 4; a++)
        #pragma unroll
        for (int b = 0; b < 2; b++) wmma::fill_fragment(acc[a][b], 0.0f);

    const uint4* gx = (const uint4*)g_xn;   // 8 bf16 per uint4; row = 128 uint4

    // per-thread constant part of the cooperative-load addressing
    int lrow0 = tid >> 2;              // 0..63
    int lcol  = (tid & 3) << 3;        // 0,8,16,24
    size_t aBase0 = (size_t)(by * 128 + lrow0)      * (DDIM / 8) + (lcol >> 3);
    size_t aBase1 = (size_t)(by * 128 + lrow0 + 64) * (DDIM / 8) + (lcol >> 3);
    size_t bBase0 = (size_t)(bx * 128 + lrow0)      * (DDIM / 8) + (lcol >> 3);
    size_t bBase1 = (size_t)(bx * 128 + lrow0 + 64) * (DDIM / 8) + (lcol >> 3);

    const int NIT = DDIM / BK;         // 32 K-iterations, stride BK/8=4 uint4
    uint4 ra0, ra1, rb0, rb1;          // prefetch registers

    // prologue: fetch tile 0 and stage into buffer 0
    ra0 = gx[aBase0]; ra1 = gx[aBase1];
    rb0 = gx[bBase0]; rb1 = gx[bBase1];
    *(uint4*)&As[0][lrow0     ][lcol] = ra0;
    *(uint4*)&As[0][lrow0 + 64][lcol] = ra1;
    *(uint4*)&Bs[0][lrow0     ][lcol] = rb0;
    *(uint4*)&Bs[0][lrow0 + 64][lcol] = rb1;

    for (int it = 0; it < NIT; it++) {
        // orders: (a) prior-iter MMA reads of buf[(it+1)&1] before this iter's
        // STS overwrites it; (b) STS of buf[it&1] before its MMA reads.
        __syncthreads();

        int cur = it & 1, nxt = cur ^ 1;
        bool more = (it + 1 < NIT);

        // issue next tile's global loads (latency hidden under the MMA section)
        if (more) {
            size_t o = (size_t)(it + 1) * (BK / 8);
            ra0 = gx[aBase0 + o]; ra1 = gx[aBase1 + o];
            rb0 = gx[bBase0 + o]; rb1 = gx[bBase1 + o];
        }

        #pragma unroll
        for (int ks = 0; ks < BK; ks += 16) {
            wmma::fragment<wmma::matrix_a, 16, 16, 16, __nv_bfloat16, wmma::row_major> af[4];
            wmma::fragment<wmma::matrix_b, 16, 16, 16, __nv_bfloat16, wmma::col_major> bf[2];
            #pragma unroll
            for (int a = 0; a < 4; a++)
                wmma::load_matrix_sync(af[a], &As[cur][wr * 64 + a * 16][ks], SMS);
            #pragma unroll
            for (int b = 0; b < 2; b++)
                wmma::load_matrix_sync(bf[b], &Bs[cur][wc * 32 + b * 16][ks], SMS);
            #pragma unroll
            for (int a = 0; a < 4; a++)
                #pragma unroll
                for (int b = 0; b < 2; b++)
                    wmma::mma_sync(acc[a][b], af[a], bf[b], acc[a][b]);
        }

        // stage next tile into the other buffer (overlaps trailing MMA work)
        if (more) {
            *(uint4*)&As[nxt][lrow0     ][lcol] = ra0;
            *(uint4*)&As[nxt][lrow0 + 64][lcol] = ra1;
            *(uint4*)&Bs[nxt][lrow0     ][lcol] = rb0;
            *(uint4*)&Bs[nxt][lrow0 + 64][lcol] = rb1;
        }
    }

    bool offdiag = (bx != by);
    #pragma unroll
    for (int a = 0; a < 4; a++)
        #pragma unroll
        for (int b = 0; b < 2; b++) {
            int r  = by * 128 + wr * 64 + a * 16;
            int cx = bx * 128 + wc * 32 + b * 16;
            wmma::store_matrix_sync(&g_cos[(size_t)r * NROWS + cx], acc[a][b],
                                    NROWS, wmma::mem_row_major);
            if (offdiag) {
                // mirrored tile: col_major store puts fragment (i,j) at
                // g_cos[(cx+j)*NROWS + (r+i)] — the exact transpose, bit-identical.
                wmma::store_matrix_sync(&g_cos[(size_t)cx * NROWS + r], acc[a][b],
                                        NROWS, wmma::mem_col_major);
            }
        }
}

// ---------------------------------------------------------------------------
// Kernel 3: triplet loss. One block per row pair (i, i+2048) so each
// threefry2x32 block (counter L, L+half) serves both rows at the same t.
// ---------------------------------------------------------------------------
__device__ __forceinline__ void threefry2x32_0_42(uint32_t x0, uint32_t x1,
                                                  uint32_t& o0, uint32_t& o1) {
    const uint32_t k0 = 0u, k1 = 42u;
    const uint32_t k2 = k0 ^ k1 ^ 0x1BD11BDAu;
    x0 += k0; x1 += k1;
#define TF_R(r) { x0 += x1; x1 = __funnelshift_l(x1, x1, r); x1 ^= x0; }
    TF_R(13) TF_R(15) TF_R(26) TF_R(6)
    x0 += k1; x1 += k2 + 1u;
    TF_R(17) TF_R(29) TF_R(16) TF_R(24)
    x0 += k2; x1 += k0 + 2u;
    TF_R(13) TF_R(15) TF_R(26) TF_R(6)
    x0 += k0; x1 += k1 + 3u;
    TF_R(17) TF_R(29) TF_R(16) TF_R(24)
    x0 += k1; x1 += k2 + 4u;
    TF_R(13) TF_R(15) TF_R(26) TF_R(6)
    x0 += k2; x1 += k0 + 5u;
#undef TF_R
    o0 = x0; o1 = x1;
}

// k-th class in the stable hard-negative order for row-class c (512 classes):
// |delta| descending; ties (c-d, c+d) broken by smaller column index (c-d first).
__device__ __forceinline__ int neg_col(int c, int t) {
    int k = t >> 3, off = t & 7;
    int hi = 511 - c;
    int Mv = max(c, hi), mv = min(c, hi);
    int s = Mv - mv;                    // single-sided distances
    int cls;
    if (k < s) {
        int d = Mv - k;
        cls = (c > hi) ? (c - d) : (c + d);
    } else {
        int k2 = k - s;
        int d = mv - (k2 >> 1);
        cls = (k2 & 1) ? (c + d) : (c - d);
    }
    return (cls << 3) + off;
}

__global__ __launch_bounds__(256) void loss_kernel() {
    __shared__ __align__(16) float rowA[NROWS];
    __shared__ __align__(16) float rowB[NROWS];
    __shared__ float red[8];

    int i  = blockIdx.x;          // 0..2047
    int i2 = i + 2048;
    int tid = threadIdx.x;
    int p = 7 - (i & 7);          // same for i and i+2048
    if (p == 0) {                 // invalid rows (no positives) contribute 0
        if (tid == 0) g_partial[i] = 0.0f;
        return;
    }

    const float4* rA = (const float4*)&g_cos[(size_t)i  * NROWS];
    const float4* rB = (const float4*)&g_cos[(size_t)i2 * NROWS];
    for (int x = tid; x < NROWS / 4; x += 256) {
        ((float4*)rowA)[x] = rA[x];
        ((float4*)rowB)[x] = rB[x];
    }
    __syncthreads();

    int c0 = i >> 3, c1 = c0 + 256;
    float fp = (float)p;
    int pm1 = p - 1;
    uint32_t base = (uint32_t)i * (uint32_t)NNEG;
    float s = 0.0f;

    for (int t = tid; t < NNEG; t += 256) {
        uint32_t o0, o1;
        threefry2x32_0_42(base + (uint32_t)t, base + (uint32_t)t + HALF_CNT, o0, o1);
        float u0 = __uint_as_float((o0 >> 9) | 0x3f800000u) - 1.0f;
        float u1 = __uint_as_float((o1 >> 9) | 0x3f800000u) - 1.0f;
        int r0 = min((int)(u0 * fp), pm1);
        int r1 = min((int)(u1 * fp), pm1);
        float cp0 = rowA[i  + 1 + r0];
        float cp1 = rowB[i2 + 1 + r1];
        float cn0 = rowA[neg_col(c0, t)];
        float cn1 = rowB[neg_col(c1, t)];
        // loss term: d_pos - d_neg + margin = (1-cp) - (1-cn) + m = cn - cp + m
        s += fmaxf(cn0 - cp0 + MARGIN, 0.0f);
        s += fmaxf(cn1 - cp1 + MARGIN, 0.0f);
    }

    #pragma unroll
    for (int o = 16; o; o >>= 1) s += __shfl_down_sync(0xffffffffu, s, o);
    if ((tid & 31) == 0) red[tid >> 5] = s;
    __syncthreads();
    if (tid < 8) {
        float t2 = red[tid];
        t2 += __shfl_down_sync(0xffu, t2, 4);
        t2 += __shfl_down_sync(0xffu, t2, 2);
        t2 += __shfl_down_sync(0xffu, t2, 1);
        if (tid == 0) g_partial[i] = t2;
    }
}

// ---------------------------------------------------------------------------
// Kernel 4: deterministic final reduction of 2048 block partials
// ---------------------------------------------------------------------------
__global__ __launch_bounds__(256) void reduce_kernel(float* __restrict__ out) {
    __shared__ float red[8];
    int tid = threadIdx.x;
    float s = 0.0f;
    for (int k = tid; k < 2048; k += 256) s += g_partial[k];
    #pragma unroll
    for (int o = 16; o; o >>= 1) s += __shfl_down_sync(0xffffffffu, s, o);
    if ((tid & 31) == 0) red[tid >> 5] = s;
    __syncthreads();
    if (tid < 8) {
        float t = red[tid];
        t += __shfl_down_sync(0xffu, t, 4);
        t += __shfl_down_sync(0xffu, t, 2);
        t += __shfl_down_sync(0xffu, t, 1);
        if (tid == 0) out[0] = t;
    }
}

// ---------------------------------------------------------------------------
extern "C" void kernel_launch(void* const* d_in, const int* in_sizes, int n_in,
                              void* d_out, int out_size) {
    const float* samples = (const float*)d_in[0];
    float* out = (float*)d_out;

    norm_kernel<<<NROWS, 256>>>(samples);
    gemm_kernel<<<NTRI, 256>>>();
    loss_kernel<<<2048, 256>>>();
    reduce_kernel<<<1, 256>>>(out);
}

// round 7
// speedup vs baseline: 1.7211x; 1.7211x over previous
#include <cuda_runtime.h>
#include <cuda_bf16.h>
#include <mma.h>
#include <cstdint>

using namespace nvcuda;

// Problem constants (fixed by the reference: N=4096, K=8, D=1024)
#define NROWS 4096
#define DDIM  1024
#define NNEG  3679            // int(0.9 * (4096 - 8))
#define HALF_CNT 7534592u     // (4096*3679)/2 == 2048*3679
#define MARGIN 0.15f
#define NTILE  32             // 4096/128 tiles per dim
#define NTRI   528            // NTILE*(NTILE+1)/2 upper-triangular tiles

// Scratch (device globals: allocation-free rule)
__device__ __align__(16) __nv_bfloat16 g_xn[NROWS * DDIM];           // 8 MB normalized bf16
__device__ __align__(16) float         g_cos[(size_t)NROWS * NROWS]; // 64 MB cosine matrix
__device__ float                       g_partial[2048];
__device__ unsigned int                g_count;   // zero-init; atomicInc wraps -> self-reset

// ---------------------------------------------------------------------------
// cp.async helpers (Ampere+ LDGSTS, 16B, L1-bypass)
// ---------------------------------------------------------------------------
__device__ __forceinline__ void cp_async16(void* smem, const void* gmem) {
    uint32_t s = (uint32_t)__cvta_generic_to_shared(smem);
    asm volatile("cp.async.cg.shared.global [%0], [%1], 16;\n" :: "r"(s), "l"(gmem));
}
#define CP_COMMIT()   asm volatile("cp.async.commit_group;\n" ::: "memory")
#define CP_WAIT_ALL() asm volatile("cp.async.wait_group 0;\n" ::: "memory")

// ---------------------------------------------------------------------------
// Kernel 1: row L2-normalize (with torch/jax EPS clamp) -> bf16
// ---------------------------------------------------------------------------
__global__ __launch_bounds__(256) void norm_kernel(const float* __restrict__ x) {
    __shared__ float red[8];
    int i = blockIdx.x, tid = threadIdx.x;
    float4 v = ((const float4*)(x + (size_t)i * DDIM))[tid];
    float ss = v.x * v.x + v.y * v.y + v.z * v.z + v.w * v.w;
    #pragma unroll
    for (int o = 16; o; o >>= 1) ss += __shfl_down_sync(0xffffffffu, ss, o);
    if ((tid & 31) == 0) red[tid >> 5] = ss;
    __syncthreads();
    if (tid < 8) {
        float t = red[tid];
        t += __shfl_down_sync(0xffu, t, 4);
        t += __shfl_down_sync(0xffu, t, 2);
        t += __shfl_down_sync(0xffu, t, 1);
        if (tid == 0) red[0] = t;
    }
    __syncthreads();
    float inv = 1.0f / fmaxf(sqrtf(red[0]), 1e-8f);
    __nv_bfloat162* dst = (__nv_bfloat162*)(g_xn + (size_t)i * DDIM + tid * 4);
    dst[0] = __floats2bfloat162_rn(v.x * inv, v.y * inv);
    dst[1] = __floats2bfloat162_rn(v.z * inv, v.w * inv);
}

// ---------------------------------------------------------------------------
// Kernel 2: C = Xn * Xn^T (cosine matrix), bf16 WMMA, fp32 accum.
// SYMMETRIC: 528 upper-triangular 128x128 tiles; off-diagonal tiles written
// twice (row_major + col_major transposed store, bit-identical mirror).
// cp.async 2-stage pipeline (GMEM->SMEM direct; frees prefetch registers),
// __launch_bounds__(256,2) pins regs <=128 for 2 CTAs/SM (16 warps/SM).
// ---------------------------------------------------------------------------
#define BK 32
#define SMS 40   // smem row stride (elements): 80B, 16B-multiple, conflict-free ldmatrix

__global__ __launch_bounds__(256, 2) void gemm_kernel() {
    __shared__ __align__(16) __nv_bfloat16 As[2][128][SMS];
    __shared__ __align__(16) __nv_bfloat16 Bs[2][128][SMS];

    // map linear block id -> upper-triangular (by, bx), bx >= by
    int lin = blockIdx.x;              // 0..527
    int by = 0, rem = lin;
    while (rem >= NTILE - by) { rem -= NTILE - by; by++; }
    int bx = by + rem;

    int tid = threadIdx.x;
    int warp = tid >> 5;
    int wr = warp & 1;     // M sub (64 rows)
    int wc = warp >> 1;    // N sub (32 cols)

    wmma::fragment<wmma::accumulator, 16, 16, 16, float> acc[4][2];
    #pragma unroll
    for (int a = 0; a < 4; a++)
        #pragma unroll
        for (int b = 0; b < 2; b++) wmma::fill_fragment(acc[a][b], 0.0f);

    const uint4* gx = (const uint4*)g_xn;   // 8 bf16 per uint4; row = 128 uint4

    // per-thread constant part of the cooperative-load addressing
    int lrow0 = tid >> 2;              // 0..63
    int lcol  = (tid & 3) << 3;        // 0,8,16,24
    size_t aBase0 = (size_t)(by * 128 + lrow0)      * (DDIM / 8) + (lcol >> 3);
    size_t aBase1 = (size_t)(by * 128 + lrow0 + 64) * (DDIM / 8) + (lcol >> 3);
    size_t bBase0 = (size_t)(bx * 128 + lrow0)      * (DDIM / 8) + (lcol >> 3);
    size_t bBase1 = (size_t)(bx * 128 + lrow0 + 64) * (DDIM / 8) + (lcol >> 3);

    const int NIT = DDIM / BK;         // 32 K-iterations, stride BK/8=4 uint4

    // prologue: stage tile 0 into buffer 0
    cp_async16(&As[0][lrow0     ][lcol], gx + aBase0);
    cp_async16(&As[0][lrow0 + 64][lcol], gx + aBase1);
    cp_async16(&Bs[0][lrow0     ][lcol], gx + bBase0);
    cp_async16(&Bs[0][lrow0 + 64][lcol], gx + bBase1);
    CP_COMMIT();

    for (int it = 0; it < NIT; it++) {
        CP_WAIT_ALL();        // stage `it` landed (only group in flight)
        __syncthreads();      // (a) data visible to all; (b) everyone done with
                              //     prior MMA reads of the buffer we now refill

        int cur = it & 1, nxt = cur ^ 1;
        if (it + 1 < NIT) {
            size_t o = (size_t)(it + 1) * (BK / 8);
            cp_async16(&As[nxt][lrow0     ][lcol], gx + aBase0 + o);
            cp_async16(&As[nxt][lrow0 + 64][lcol], gx + aBase1 + o);
            cp_async16(&Bs[nxt][lrow0     ][lcol], gx + bBase0 + o);
            cp_async16(&Bs[nxt][lrow0 + 64][lcol], gx + bBase1 + o);
            CP_COMMIT();
        }

        #pragma unroll
        for (int ks = 0; ks < BK; ks += 16) {
            wmma::fragment<wmma::matrix_a, 16, 16, 16, __nv_bfloat16, wmma::row_major> af[4];
            wmma::fragment<wmma::matrix_b, 16, 16, 16, __nv_bfloat16, wmma::col_major> bf[2];
            #pragma unroll
            for (int a = 0; a < 4; a++)
                wmma::load_matrix_sync(af[a], &As[cur][wr * 64 + a * 16][ks], SMS);
            #pragma unroll
            for (int b = 0; b < 2; b++)
                wmma::load_matrix_sync(bf[b], &Bs[cur][wc * 32 + b * 16][ks], SMS);
            #pragma unroll
            for (int a = 0; a < 4; a++)
                #pragma unroll
                for (int b = 0; b < 2; b++)
                    wmma::mma_sync(acc[a][b], af[a], bf[b], acc[a][b]);
        }
    }

    bool offdiag = (bx != by);
    #pragma unroll
    for (int a = 0; a < 4; a++)
        #pragma unroll
        for (int b = 0; b < 2; b++) {
            int r  = by * 128 + wr * 64 + a * 16;
            int cx = bx * 128 + wc * 32 + b * 16;
            wmma::store_matrix_sync(&g_cos[(size_t)r * NROWS + cx], acc[a][b],
                                    NROWS, wmma::mem_row_major);
            if (offdiag) {
                // mirrored tile: col_major store puts fragment (i,j) at
                // g_cos[(cx+j)*NROWS + (r+i)] — the exact transpose, bit-identical.
                wmma::store_matrix_sync(&g_cos[(size_t)cx * NROWS + r], acc[a][b],
                                        NROWS, wmma::mem_col_major);
            }
        }
}

// ---------------------------------------------------------------------------
// Kernel 3: triplet loss + fused final reduction (last-block-done pattern).
// One block per row pair (i, i+2048) so each threefry2x32 block (counter
// L, L+half) serves both rows at the same t.
// ---------------------------------------------------------------------------
__device__ __forceinline__ void threefry2x32_0_42(uint32_t x0, uint32_t x1,
                                                  uint32_t& o0, uint32_t& o1) {
    const uint32_t k0 = 0u, k1 = 42u;
    const uint32_t k2 = k0 ^ k1 ^ 0x1BD11BDAu;
    x0 += k0; x1 += k1;
#define TF_R(r) { x0 += x1; x1 = __funnelshift_l(x1, x1, r); x1 ^= x0; }
    TF_R(13) TF_R(15) TF_R(26) TF_R(6)
    x0 += k1; x1 += k2 + 1u;
    TF_R(17) TF_R(29) TF_R(16) TF_R(24)
    x0 += k2; x1 += k0 + 2u;
    TF_R(13) TF_R(15) TF_R(26) TF_R(6)
    x0 += k0; x1 += k1 + 3u;
    TF_R(17) TF_R(29) TF_R(16) TF_R(24)
    x0 += k1; x1 += k2 + 4u;
    TF_R(13) TF_R(15) TF_R(26) TF_R(6)
    x0 += k2; x1 += k0 + 5u;
#undef TF_R
    o0 = x0; o1 = x1;
}

// k-th class in the stable hard-negative order for row-class c (512 classes):
// |delta| descending; ties (c-d, c+d) broken by smaller column index (c-d first).
__device__ __forceinline__ int neg_col(int c, int t) {
    int k = t >> 3, off = t & 7;
    int hi = 511 - c;
    int Mv = max(c, hi), mv = min(c, hi);
    int s = Mv - mv;                    // single-sided distances
    int cls;
    if (k < s) {
        int d = Mv - k;
        cls = (c > hi) ? (c - d) : (c + d);
    } else {
        int k2 = k - s;
        int d = mv - (k2 >> 1);
        cls = (k2 & 1) ? (c + d) : (c - d);
    }
    return (cls << 3) + off;
}

__global__ __launch_bounds__(256) void loss_kernel(float* __restrict__ out) {
    __shared__ __align__(16) float rowA[NROWS];
    __shared__ __align__(16) float rowB[NROWS];
    __shared__ float red[8];
    __shared__ bool isLast;

    int i  = blockIdx.x;          // 0..2047
    int i2 = i + 2048;
    int tid = threadIdx.x;
    int p = 7 - (i & 7);          // same for i and i+2048

    float s = 0.0f;
    if (p != 0) {                 // rows with no positives contribute 0
        const float4* rA = (const float4*)&g_cos[(size_t)i  * NROWS];
        const float4* rB = (const float4*)&g_cos[(size_t)i2 * NROWS];
        for (int x = tid; x < NROWS / 4; x += 256) {
            ((float4*)rowA)[x] = rA[x];
            ((float4*)rowB)[x] = rB[x];
        }
        __syncthreads();

        int c0 = i >> 3, c1 = c0 + 256;
        float fp = (float)p;
        int pm1 = p - 1;
        uint32_t base = (uint32_t)i * (uint32_t)NNEG;

        for (int t = tid; t < NNEG; t += 256) {
            uint32_t o0, o1;
            threefry2x32_0_42(base + (uint32_t)t, base + (uint32_t)t + HALF_CNT, o0, o1);
            float u0 = __uint_as_float((o0 >> 9) | 0x3f800000u) - 1.0f;
            float u1 = __uint_as_float((o1 >> 9) | 0x3f800000u) - 1.0f;
            int r0 = min((int)(u0 * fp), pm1);
            int r1 = min((int)(u1 * fp), pm1);
            float cp0 = rowA[i  + 1 + r0];
            float cp1 = rowB[i2 + 1 + r1];
            float cn0 = rowA[neg_col(c0, t)];
            float cn1 = rowB[neg_col(c1, t)];
            // loss term: d_pos - d_neg + margin = (1-cp) - (1-cn) + m = cn - cp + m
            s += fmaxf(cn0 - cp0 + MARGIN, 0.0f);
            s += fmaxf(cn1 - cp1 + MARGIN, 0.0f);
        }
    }

    #pragma unroll
    for (int o = 16; o; o >>= 1) s += __shfl_down_sync(0xffffffffu, s, o);
    if ((tid & 31) == 0) red[tid >> 5] = s;
    __syncthreads();
    if (tid < 8) {
        float t2 = red[tid];
        t2 += __shfl_down_sync(0xffu, t2, 4);
        t2 += __shfl_down_sync(0xffu, t2, 2);
        t2 += __shfl_down_sync(0xffu, t2, 1);
        if (tid == 0) g_partial[i] = t2;
    }

    // last-block-done final reduction (deterministic: one block, fixed order;
    // atomicInc wraps 2047 -> 0 so the counter self-resets every call)
    __threadfence();
    if (tid == 0) {
        unsigned v = atomicInc(&g_count, 2047u);
        isLast = (v == 2047u);
    }
    __syncthreads();
    if (isLast) {
        float s2 = 0.0f;
        for (int k = tid; k < 2048; k += 256) s2 += g_partial[k];
        #pragma unroll
        for (int o = 16; o; o >>= 1) s2 += __shfl_down_sync(0xffffffffu, s2, o);
        if ((tid & 31) == 0) red[tid >> 5] = s2;
        __syncthreads();
        if (tid < 8) {
            float t2 = red[tid];
            t2 += __shfl_down_sync(0xffu, t2, 4);
            t2 += __shfl_down_sync(0xffu, t2, 2);
            t2 += __shfl_down_sync(0xffu, t2, 1);
            if (tid == 0) out[0] = t2;
        }
    }
}

// ---------------------------------------------------------------------------
extern "C" void kernel_launch(void* const* d_in, const int* in_sizes, int n_in,
                              void* d_out, int out_size) {
    const float* samples = (const float*)d_in[0];
    float* out = (float*)d_out;

    norm_kernel<<<NROWS, 256>>>(samples);
    gemm_kernel<<<NTRI, 256>>>();
    loss_kernel<<<2048, 256>>>(out);
}